// round 13
// baseline (speedup 1.0000x reference)
#include <cuda_runtime.h>
#include <cuda_bf16.h>
#include <math.h>
#include <stdint.h>

// ---------------------------------------------------------------------------
// LearningNMS — bf16 mma.sync pipelined + separable geometry + fused tail
//   (grid-barrier fuses bn1red + fout/final into k_main; 7 launches total)
//   G=512, D=64, H=128, NB=2, P=136, FH=128
// ---------------------------------------------------------------------------

namespace {
constexpr int G   = 512;
constexpr int H   = 128;
constexpr int DP1 = 65;
constexpr int P   = 136;
constexpr int FH  = 128;
constexpr int JT  = 32;
constexpr int SWP = 68;     // uint32 (bf16x2) stride; 68 % 32 = 4 -> bank permute
constexpr int H1B = JT * SWP * 4;
constexpr int W1_U32  = H * SWP;
constexpr int H1_U32  = 2 * JT * SWP;
constexpr int SMEM_MAIN = (W1_U32 + H1_U32 + 2 * JT) * 4;  // ~52.7KB
constexpr float EPS    = 1e-3f;
constexpr float IOU_T  = 0.3f;
constexpr float INV_N  = 1.0f / (512.0f * 512.0f);
constexpr float INV_G  = 1.0f / 512.0f;
}

// -------------------- scratch (device globals; no allocs) -------------------
__device__ float g_bp[G * 12];
__device__ float g_f[G * DP1];
__device__ float g_gpart[G * 12];
__device__ float g_geomstat[12];
__device__ float g_fstat[2 * DP1];
__device__ float g_W0g[6 * H];
__device__ float g_cb[H];
__device__ float g_u[G * H];
__device__ float g_v[G * H];
__device__ float g_sums[G * H];
__device__ float g_sumsq[G * H];
__device__ float g_maxv[G * H];
__device__ float g_minv[G * H];
__device__ float g_bn1[2 * H];
__device__ unsigned int g_barrier[2];   // monotonic generation counters

// -------------------- helpers ------------------------------------------------
struct BoxI { float x, y, x2, y2, cx, cy, ar, lw, lh, la, rw, rh; };

__device__ __forceinline__ BoxI loadbox_p(const float* bp) {
    BoxI b;
    b.x = bp[0];  b.y = bp[1];  b.x2 = bp[2]; b.y2 = bp[3];
    b.cx = bp[4]; b.cy = bp[5]; b.ar = bp[6];
    b.lw = bp[7]; b.lh = bp[8]; b.la = bp[9];
    b.rw = bp[10]; b.rh = bp[11];
    return b;
}

__device__ __forceinline__ void geom6(const BoxI& a, const BoxI& b, float* g) {
    float ix1 = fmaxf(a.x,  b.x),  iy1 = fmaxf(a.y,  b.y);
    float ix2 = fminf(a.x2, b.x2), iy2 = fminf(a.y2, b.y2);
    float inter = fmaxf(ix2 - ix1, 0.0f) * fmaxf(iy2 - iy1, 0.0f);
    g[0] = inter / (a.ar + b.ar - inter + 1e-6f);
    g[1] = (a.cx - b.cx) * a.rw;
    g[2] = (a.cy - b.cy) * a.rh;
    g[3] = b.lw - a.lw;
    g[4] = b.lh - a.lh;
    g[5] = b.la - a.la;
}

__device__ __forceinline__ void mma_bf16(float* c, const uint32_t* a, const uint32_t* b) {
    asm volatile(
        "mma.sync.aligned.m16n8k16.row.col.f32.bf16.bf16.f32 "
        "{%0,%1,%2,%3}, {%4,%5,%6,%7}, {%8,%9}, {%0,%1,%2,%3};"
        : "+f"(c[0]), "+f"(c[1]), "+f"(c[2]), "+f"(c[3])
        : "r"(a[0]), "r"(a[1]), "r"(a[2]), "r"(a[3]), "r"(b[0]), "r"(b[1]));
}

__device__ __forceinline__ void ldmx4(uint32_t& r0, uint32_t& r1,
                                      uint32_t& r2, uint32_t& r3, uint32_t addr) {
    asm volatile("ldmatrix.sync.aligned.m8n8.x4.shared.b16 {%0,%1,%2,%3}, [%4];"
                 : "=r"(r0), "=r"(r1), "=r"(r2), "=r"(r3) : "r"(addr));
}

__device__ __forceinline__ uint32_t packbf2(float lo, float hi) {
    __nv_bfloat162 v = __floats2bfloat162_rn(lo, hi);
    return *(uint32_t*)&v;
}

// Grid barrier: monotonic counter, generation = v/512 (replay-safe, no reset).
// Requires all 512 CTAs resident (guaranteed: __launch_bounds__(128,4) -> 592 slots).
__device__ __forceinline__ void grid_barrier(unsigned int* ctr) {
    __syncthreads();
    if (threadIdx.x == 0) {
        __threadfence();
        unsigned int v = atomicAdd(ctr, 1u);
        unsigned int target = (v / 512u + 1u) * 512u;
        while (true) {
            unsigned int cur;
            asm volatile("ld.global.acquire.gpu.u32 %0, [%1];"
                         : "=r"(cur) : "l"(ctr));
            if (cur >= target) break;
            __nanosleep(64);
        }
    }
    __syncthreads();
}

// -------------------- geom stats (fused boxprep) ------------------------------
__global__ void k_geomstats(const float* __restrict__ boxes,
                            const float* __restrict__ scores,
                            const float* __restrict__ feats) {
    __shared__ float bps[G * 12];
    __shared__ float red[12 * 256];
    int i = blockIdx.x, tid = threadIdx.x;

    for (int b = tid; b < G; b += 256) {
        float x = boxes[b*4+0], y = boxes[b*4+1], w = boxes[b*4+2], h = boxes[b*4+3];
        float* bp = &bps[b * 12];
        bp[0] = x;          bp[1] = y;
        bp[2] = x + w;      bp[3] = y + h;
        bp[4] = x + 0.5f*w; bp[5] = y + 0.5f*h;
        bp[6] = w * h;
        bp[7] = logf(w);    bp[8] = logf(h);  bp[9] = logf(w * h);
        bp[10] = 1.0f / w;  bp[11] = 1.0f / h;
        if (i == 0) {
            #pragma unroll
            for (int m = 0; m < 12; m++) g_bp[b * 12 + m] = bp[m];
            g_f[b * DP1] = scores[b];
        }
    }
    if (i == 0) {
        for (int idx = tid; idx < G * 64; idx += 256) {
            int r = idx >> 6, d = idx & 63;
            g_f[r * DP1 + 1 + d] = feats[idx];
        }
    }
    __syncthreads();

    BoxI bi = loadbox_p(&bps[i * 12]);
    float ls[6] = {0,0,0,0,0,0}, lq[6] = {0,0,0,0,0,0};
    for (int j = tid; j < G; j += 256) {
        BoxI bj = loadbox_p(&bps[j * 12]);
        float g[6]; geom6(bi, bj, g);
        #pragma unroll
        for (int m = 0; m < 6; m++) { ls[m] += g[m]; lq[m] += g[m]*g[m]; }
    }
    #pragma unroll
    for (int m = 0; m < 6; m++) { red[m*256 + tid] = ls[m]; red[(6+m)*256 + tid] = lq[m]; }
    __syncthreads();
    for (int s = 128; s > 0; s >>= 1) {
        if (tid < s) {
            #pragma unroll
            for (int m = 0; m < 12; m++) red[m*256 + tid] += red[m*256 + tid + s];
        }
        __syncthreads();
    }
    if (tid == 0) {
        #pragma unroll
        for (int m = 0; m < 12; m++) g_gpart[i*12 + m] = red[m*256];
    }
}

// fused: (first: geomred) + f stats + BN0-fold into W0
__global__ void k_fstats_prepw(const float* __restrict__ W0k, const float* __restrict__ b0k,
                               const float* __restrict__ g0k, const float* __restrict__ bb0k,
                               int first) {
    __shared__ float sred[2][8][DP1 + 1];
    __shared__ float part[8][128];
    __shared__ float ws[12];
    int x = threadIdx.x, y = threadIdx.y;
    int t = y * 128 + x;

    if (first && t < 384) {
        int m = t >> 5, l = t & 31;
        float s = 0.0f;
        for (int i = l; i < G; i += 32) s += g_gpart[i * 12 + m];
        #pragma unroll
        for (int d = 16; d > 0; d >>= 1) s += __shfl_xor_sync(0xffffffffu, s, d);
        if (l == 0) ws[m] = s;
    }
    {
        int col = t & 127, chunk = t >> 7;
        if (col < DP1) {
            float s = 0.0f, q = 0.0f;
            #pragma unroll 8
            for (int r = chunk * 64; r < chunk * 64 + 64; r++) {
                float v = g_f[r * DP1 + col];
                s += v; q = fmaf(v, v, q);
            }
            sred[0][chunk][col] = s;
            sred[1][chunk][col] = q;
        }
    }
    __syncthreads();
    if (first && t < 6) {
        float mean = ws[t] * INV_N;
        float var  = fmaxf(ws[6 + t] * INV_N - mean * mean, 0.0f);
        g_geomstat[t] = mean; g_geomstat[6 + t] = var;
    }
    if (t < DP1) {
        float s = 0.0f, q = 0.0f;
        #pragma unroll
        for (int k = 0; k < 8; k++) { s += sred[0][k][t]; q += sred[1][k][t]; }
        float mean = s * INV_G;
        float var  = fmaxf(q * INV_G - mean * mean, 0.0f);
        g_fstat[t] = mean; g_fstat[DP1 + t] = var;
    }
    __syncthreads();

    int c = x, yy = y;
    float cb = 0.0f;
    int r0 = yy * 17;
    #pragma unroll
    for (int rr = 0; rr < 17; rr++) {
        int r = r0 + rr;
        float m, vv;
        if (r < 6) { m = g_geomstat[r]; vv = g_geomstat[6 + r]; }
        else       { int d = (r < 71) ? r - 6 : r - 71;
                     m = g_fstat[d];   vv = g_fstat[DP1 + d]; }
        float s0 = g0k[r] * rsqrtf(vv + EPS);
        float sh = bb0k[r] - m * s0;
        float wv = W0k[r * H + c];
        cb += sh * wv;
        if (r < 6) g_W0g[r * H + c] = s0 * wv;
    }
    part[yy][c] = cb;
    __syncthreads();
    if (yy == 0) {
        float tt = b0k[c];
        #pragma unroll
        for (int k = 0; k < 8; k++) tt += part[k][c];
        g_cb[c] = tt;
    }
}

// u'[i,c], v'[j,c] with separable geometry folded in
__global__ void k_uv(const float* __restrict__ W0k, const float* __restrict__ g0k) {
    __shared__ float fi[DP1], sA[DP1], sB[DP1];
    int i = blockIdx.x, c = threadIdx.x;
    if (c < DP1) {
        fi[c] = g_f[i * DP1 + c];
        float rs = rsqrtf(g_fstat[DP1 + c] + EPS);
        sA[c] = g0k[6 + c]  * rs;
        sB[c] = g0k[71 + c] * rs;
    }
    __syncthreads();
    float u = g_cb[c], v = 0.0f;
    for (int d = 0; d < DP1; d++) {
        float fd = fi[d];
        u = fmaf(fd * sA[d], W0k[(6  + d) * H + c], u);
        v = fmaf(fd * sB[d], W0k[(71 + d) * H + c], v);
    }
    const float* bp = &g_bp[i * 12];
    float cxr = bp[4] * bp[10], cyr = bp[5] * bp[11];
    float lw = bp[7], lh = bp[8], la = bp[9];
    float w1 = g_W0g[H + c],     w2 = g_W0g[2*H + c];
    float w3 = g_W0g[3*H + c],   w4 = g_W0g[4*H + c], w5 = g_W0g[5*H + c];
    float sep = lw * w3 + lh * w4 + la * w5;
    u += cxr * w1 + cyr * w2 - sep;
    v += sep;
    g_u[i * H + c] = u;
    g_v[i * H + c] = v;
}

// -------------------- main pair kernel + fused tail --------------------------
__global__ void __launch_bounds__(128, 4) k_main(
    const float* __restrict__ W1k,  const float* __restrict__ b1k,
    const float* __restrict__ g1k,  const float* __restrict__ b1nk,
    const float* __restrict__ Woutk, const float* __restrict__ boutk,
    const float* __restrict__ Wf0,  const float* __restrict__ bf0,
    const float* __restrict__ Wf1,  const float* __restrict__ bf1,
    const float* __restrict__ Wsc,  const float* __restrict__ bsc,
    float* __restrict__ out, int is_final) {
    extern __shared__ uint32_t smu[];
    uint32_t* W1p = smu;                                   // [H][SWP]
    uint32_t* h1p = smu + W1_U32;                          // [2][JT][SWP]
    float*    mask_s = (float*)(smu + W1_U32 + H1_U32);    // [2][JT]

    int i = blockIdx.x, tid = threadIdx.x;
    int lane = tid & 31, wrp = tid >> 5;
    int gid = lane >> 2, tig = lane & 3;
    int nbase = wrp * 32;
    int cpair = tid & 63;
    int half  = tid >> 6;

    {
        int c = tid;
        #pragma unroll 8
        for (int kk = 0; kk < 64; kk++)
            W1p[c * SWP + kk] = packbf2(W1k[(2 * kk) * H + c],
                                        W1k[(2 * kk + 1) * H + c]);
    }

    uint32_t h1_base = (uint32_t)__cvta_generic_to_shared(h1p);
    uint32_t w1_base = (uint32_t)__cvta_generic_to_shared(W1p);
    uint32_t aaddr[2], baddr[2];
    #pragma unroll
    for (int mi = 0; mi < 2; mi++)
        aaddr[mi] = h1_base
            + (((mi * 16 + (lane & 15)) * SWP + ((lane >> 4) << 2)) << 2);
    #pragma unroll
    for (int bi = 0; bi < 2; bi++)
        baddr[bi] = w1_base
            + (((nbase + bi * 16 + (lane & 7) + ((lane >> 4) << 3)) * SWP
                + (((lane >> 3) & 1) << 2)) << 2);

    const float* bpi = &g_bp[i * 12];
    float4 bi0 = *(const float4*)bpi;
    float ari = bpi[6], rwi = bpi[10], rhi = bpi[11];
    float ua = g_u[i * H + 2 * cpair];
    float ub = g_u[i * H + 2 * cpair + 1];
    float wioua = g_W0g[2 * cpair],           wioub = g_W0g[2 * cpair + 1];
    float wdxa = -rwi * g_W0g[H + 2*cpair],   wdxb = -rwi * g_W0g[H + 2*cpair + 1];
    float wdya = -rhi * g_W0g[2*H + 2*cpair], wdyb = -rhi * g_W0g[2*H + 2*cpair + 1];

    float bias[4][2];
    #pragma unroll
    for (int ni = 0; ni < 4; ni++)
        #pragma unroll
        for (int q = 0; q < 2; q++)
            bias[ni][q] = b1k[nbase + ni * 8 + 2 * tig + q];

    float S[4][2], Qa[4][2], Mx[4][2], Mn[4][2];
    #pragma unroll
    for (int ni = 0; ni < 4; ni++)
        #pragma unroll
        for (int q = 0; q < 2; q++) {
            S[ni][q] = 0.0f; Qa[ni][q] = 0.0f;
            Mx[ni][q] = -INFINITY; Mn[ni][q] = INFINITY;
        }

    auto produce = [&](int t, int b) {
        int j0 = t * JT;
        int jl = half * 16 + (lane & 15);
        const float* bpj = &g_bp[(j0 + jl) * 12];
        float4 j0f = *(const float4*)bpj;
        float4 j1f = *(const float4*)(bpj + 4);
        float ix1 = fmaxf(bi0.x, j0f.x), iy1 = fmaxf(bi0.y, j0f.y);
        float ix2 = fminf(bi0.z, j0f.z), iy2 = fminf(bi0.w, j0f.w);
        float inter = fmaxf(ix2 - ix1, 0.0f) * fmaxf(iy2 - iy1, 0.0f);
        float iou = inter / (ari + j1f.z - inter + 1e-6f);
        float cxj = j1f.x, cyj = j1f.y;
        if ((wrp & 1) == 0 && lane < 16)
            mask_s[b * JT + jl] = (iou > IOU_T) ? 1.0f : 0.0f;
        #pragma unroll
        for (int jj = 0; jj < 16; jj++) {
            float io = __shfl_sync(0xffffffffu, iou, jj);
            float cj = __shfl_sync(0xffffffffu, cxj, jj);
            float dj = __shfl_sync(0xffffffffu, cyj, jj);
            int j = half * 16 + jj;
            float2 vf = *(const float2*)&g_v[(j0 + j) * H + 2 * cpair];
            float a0 = ua + vf.x, a1 = ub + vf.y;
            a0 = fmaf(io, wioua, a0);  a1 = fmaf(io, wioub, a1);
            a0 = fmaf(cj, wdxa, a0);   a1 = fmaf(cj, wdxb, a1);
            a0 = fmaf(dj, wdya, a0);   a1 = fmaf(dj, wdyb, a1);
            h1p[(b * JT + j) * SWP + cpair] = packbf2(fmaxf(a0, 0.0f),
                                                      fmaxf(a1, 0.0f));
        }
    };

    produce(0, 0);

    for (int t = 0; t < 16; t++) {
        __syncthreads();
        if (t < 15) produce(t + 1, (t + 1) & 1);

        uint32_t boff = (t & 1) * H1B;

        float acc[2][4][4];
        #pragma unroll
        for (int mi = 0; mi < 2; mi++)
            #pragma unroll
            for (int ni = 0; ni < 4; ni++)
                #pragma unroll
                for (int q = 0; q < 4; q++) acc[mi][ni][q] = 0.0f;

        #pragma unroll
        for (int ki = 0; ki < 8; ki++) {
            uint32_t a[2][4], b[4][2];
            #pragma unroll
            for (int mi = 0; mi < 2; mi++)
                ldmx4(a[mi][0], a[mi][1], a[mi][2], a[mi][3],
                      aaddr[mi] + boff + ki * 32);
            #pragma unroll
            for (int bj = 0; bj < 2; bj++)
                ldmx4(b[2*bj][0], b[2*bj][1], b[2*bj+1][0], b[2*bj+1][1],
                      baddr[bj] + ki * 32);
            #pragma unroll
            for (int mi = 0; mi < 2; mi++)
                #pragma unroll
                for (int ni = 0; ni < 4; ni++)
                    mma_bf16(acc[mi][ni], a[mi], b[ni]);
        }

        #pragma unroll
        for (int mi = 0; mi < 2; mi++) {
            float m0 = mask_s[(t & 1) * JT + mi * 16 + gid];
            float m1 = mask_s[(t & 1) * JT + mi * 16 + gid + 8];
            #pragma unroll
            for (int ni = 0; ni < 4; ni++) {
                #pragma unroll
                for (int q = 0; q < 2; q++) {
                    float h0 = fmaxf(acc[mi][ni][q]     + bias[ni][q], 0.0f);
                    float h1 = fmaxf(acc[mi][ni][q + 2] + bias[ni][q], 0.0f);
                    S[ni][q] += h0 + h1;
                    Qa[ni][q] = fmaf(h0, h0, Qa[ni][q]);
                    Qa[ni][q] = fmaf(h1, h1, Qa[ni][q]);
                    if (m0 > 0.5f) { Mx[ni][q] = fmaxf(Mx[ni][q], h0); Mn[ni][q] = fminf(Mn[ni][q], h0); }
                    if (m1 > 0.5f) { Mx[ni][q] = fmaxf(Mx[ni][q], h1); Mn[ni][q] = fminf(Mn[ni][q], h1); }
                }
            }
        }
    }

    #pragma unroll
    for (int ni = 0; ni < 4; ni++)
        #pragma unroll
        for (int q = 0; q < 2; q++) {
            #pragma unroll
            for (int d = 4; d <= 16; d <<= 1) {
                S[ni][q]  += __shfl_xor_sync(0xffffffffu, S[ni][q],  d);
                Qa[ni][q] += __shfl_xor_sync(0xffffffffu, Qa[ni][q], d);
                Mx[ni][q] = fmaxf(Mx[ni][q], __shfl_xor_sync(0xffffffffu, Mx[ni][q], d));
                Mn[ni][q] = fminf(Mn[ni][q], __shfl_xor_sync(0xffffffffu, Mn[ni][q], d));
            }
        }
    if (gid == 0) {
        #pragma unroll
        for (int ni = 0; ni < 4; ni++)
            #pragma unroll
            for (int q = 0; q < 2; q++) {
                int c = nbase + ni * 8 + 2 * tig + q;
                g_sums[i * H + c]  = S[ni][q];
                g_sumsq[i * H + c] = Qa[ni][q];
                g_maxv[i * H + c]  = Mx[ni][q];
                g_minv[i * H + c]  = Mn[ni][q];
            }
    }

    // ---------------- fused tail: bn1red -> fout(/final) --------------------
    grid_barrier(&g_barrier[0]);

    if (i == 0) {
        int c = tid;
        float s = 0.0f, q = 0.0f;
        #pragma unroll 4
        for (int r = 0; r < G; r++) {
            s += g_sums[r * H + c];
            q += g_sumsq[r * H + c];
        }
        float mean = s * INV_N;
        float var  = fmaxf(q * INV_N - mean * mean, 0.0f);
        float sc = g1k[c] * rsqrtf(var + EPS);
        g_bn1[c]     = sc;
        g_bn1[H + c] = b1nk[c] - mean * sc;
    }

    grid_barrier(&g_barrier[1]);

    float* p = (float*)h1p;      // reuse smem
    {
        int t = tid;
        float sc = g_bn1[t];
        p[t] = ((sc >= 0.0f) ? sc * g_maxv[i * H + t] : sc * g_minv[i * H + t])
               + g_bn1[H + t];
    }
    __syncthreads();
    if (!is_final) {
        int t = tid;
        if (t < DP1) {
            float acc = boutk[t];
            for (int c = 0; c < H; c++) acc = fmaf(p[c], Woutk[c * DP1 + t], acc);
            g_f[i * DP1 + t] = acc;
        }
    } else {
        float* fr = p + H;
        float* y1 = fr + DP1;
        float* rb = y1 + FH;
        int t = tid;
        if (t < DP1) {
            float acc = boutk[t];
            for (int c = 0; c < H; c++) acc = fmaf(p[c], Woutk[c * DP1 + t], acc);
            fr[t] = acc;
        }
        __syncthreads();
        float a = bf0[t];
        for (int d = 0; d < DP1; d++) a = fmaf(fr[d], Wf0[d * FH + t], a);
        y1[t] = fmaxf(a, 0.0f);
        __syncthreads();
        float b = bf1[t];
        for (int d = 0; d < FH; d++) b = fmaf(y1[d], Wf1[d * FH + t], b);
        float y2 = fmaxf(b, 0.0f);
        rb[t] = y2 * Wsc[t];
        __syncthreads();
        for (int s = 64; s > 0; s >>= 1) {
            if (t < s) rb[t] += rb[t + s];
            __syncthreads();
        }
        if (t == 0) out[i] = 1.0f / (1.0f + expf(-(rb[0] + bsc[0])));
    }
}

// -------------------- launch -------------------------------------------------
extern "C" void kernel_launch(void* const* d_in, const int* in_sizes, int n_in,
                              void* d_out, int out_size) {
    const float* boxes  = (const float*)d_in[0];
    const float* scores = (const float*)d_in[1];
    const float* feats  = (const float*)d_in[2];
    const float* bn0_g  = (const float*)d_in[3];
    const float* bn0_b  = (const float*)d_in[4];
    const float* W0     = (const float*)d_in[5];
    const float* b0     = (const float*)d_in[6];
    const float* W1     = (const float*)d_in[7];
    const float* b1     = (const float*)d_in[8];
    const float* bn1_g  = (const float*)d_in[9];
    const float* bn1_b  = (const float*)d_in[10];
    const float* Wout   = (const float*)d_in[11];
    const float* bout   = (const float*)d_in[12];
    const float* Wf0    = (const float*)d_in[13];
    const float* bf0    = (const float*)d_in[14];
    const float* Wf1    = (const float*)d_in[15];
    const float* bf1    = (const float*)d_in[16];
    const float* Wsc    = (const float*)d_in[17];
    const float* bsc    = (const float*)d_in[18];
    float* out = (float*)d_out;

    cudaFuncSetAttribute(k_main, cudaFuncAttributeMaxDynamicSharedMemorySize,
                         SMEM_MAIN);

    k_geomstats<<<512, 256>>>(boxes, scores, feats);

    for (int k = 0; k < 2; k++) {
        const float* W0k   = W0 + (size_t)k * P * H;
        const float* b0k   = b0 + k * H;
        const float* g0k   = bn0_g + k * P;
        const float* bb0k  = bn0_b + k * P;
        const float* W1k   = W1 + (size_t)k * H * H;
        const float* b1k   = b1 + k * H;
        const float* g1k   = bn1_g + k * H;
        const float* b1nk  = bn1_b + k * H;
        const float* Woutk = Wout + (size_t)k * H * DP1;
        const float* boutk = bout + k * DP1;

        k_fstats_prepw<<<1, dim3(128, 8)>>>(W0k, b0k, g0k, bb0k, k == 0 ? 1 : 0);
        k_uv<<<512, 128>>>(W0k, g0k);
        k_main<<<512, 128, SMEM_MAIN>>>(W1k, b1k, g1k, b1nk, Woutk, boutk,
                                        Wf0, bf0, Wf1, bf1, Wsc, bsc,
                                        out, k);
    }
}

// round 14
// speedup vs baseline: 1.5530x; 1.5530x over previous
#include <cuda_runtime.h>
#include <cuda_bf16.h>
#include <math.h>
#include <stdint.h>

// ---------------------------------------------------------------------------
// LearningNMS — bf16 mma.sync pipelined + separable-geometry factorization
//   (Round-8 champion structure; bn1red parallelized across 128 blocks)
//   G=512, D=64, H=128, NB=2, P=136, FH=128
// ---------------------------------------------------------------------------

namespace {
constexpr int G   = 512;
constexpr int H   = 128;
constexpr int DP1 = 65;
constexpr int P   = 136;
constexpr int FH  = 128;
constexpr int JT  = 32;
constexpr int SWP = 68;     // uint32 (bf16x2) stride; 68 % 32 = 4 -> bank permute
constexpr int H1B = JT * SWP * 4;
constexpr int W1_U32  = H * SWP;
constexpr int H1_U32  = 2 * JT * SWP;
constexpr int SMEM_MAIN = (W1_U32 + H1_U32 + 2 * JT) * 4;  // ~52.7KB
constexpr float EPS    = 1e-3f;
constexpr float IOU_T  = 0.3f;
constexpr float INV_N  = 1.0f / (512.0f * 512.0f);
constexpr float INV_G  = 1.0f / 512.0f;
}

// -------------------- scratch (device globals; no allocs) -------------------
__device__ float g_bp[G * 12];
__device__ float g_f[G * DP1];
__device__ float g_gpart[G * 12];
__device__ float g_geomstat[12];
__device__ float g_fstat[2 * DP1];
__device__ float g_W0g[6 * H];
__device__ float g_cb[H];
__device__ float g_u[G * H];
__device__ float g_v[G * H];
__device__ float g_sums[G * H];
__device__ float g_sumsq[G * H];
__device__ float g_maxv[G * H];
__device__ float g_minv[G * H];
__device__ float g_bn1[2 * H];

// -------------------- helpers ------------------------------------------------
struct BoxI { float x, y, x2, y2, cx, cy, ar, lw, lh, la, rw, rh; };

__device__ __forceinline__ BoxI loadbox_p(const float* bp) {
    BoxI b;
    b.x = bp[0];  b.y = bp[1];  b.x2 = bp[2]; b.y2 = bp[3];
    b.cx = bp[4]; b.cy = bp[5]; b.ar = bp[6];
    b.lw = bp[7]; b.lh = bp[8]; b.la = bp[9];
    b.rw = bp[10]; b.rh = bp[11];
    return b;
}

__device__ __forceinline__ void geom6(const BoxI& a, const BoxI& b, float* g) {
    float ix1 = fmaxf(a.x,  b.x),  iy1 = fmaxf(a.y,  b.y);
    float ix2 = fminf(a.x2, b.x2), iy2 = fminf(a.y2, b.y2);
    float inter = fmaxf(ix2 - ix1, 0.0f) * fmaxf(iy2 - iy1, 0.0f);
    g[0] = inter / (a.ar + b.ar - inter + 1e-6f);
    g[1] = (a.cx - b.cx) * a.rw;
    g[2] = (a.cy - b.cy) * a.rh;
    g[3] = b.lw - a.lw;
    g[4] = b.lh - a.lh;
    g[5] = b.la - a.la;
}

__device__ __forceinline__ void mma_bf16(float* c, const uint32_t* a, const uint32_t* b) {
    asm volatile(
        "mma.sync.aligned.m16n8k16.row.col.f32.bf16.bf16.f32 "
        "{%0,%1,%2,%3}, {%4,%5,%6,%7}, {%8,%9}, {%0,%1,%2,%3};"
        : "+f"(c[0]), "+f"(c[1]), "+f"(c[2]), "+f"(c[3])
        : "r"(a[0]), "r"(a[1]), "r"(a[2]), "r"(a[3]), "r"(b[0]), "r"(b[1]));
}

__device__ __forceinline__ void ldmx4(uint32_t& r0, uint32_t& r1,
                                      uint32_t& r2, uint32_t& r3, uint32_t addr) {
    asm volatile("ldmatrix.sync.aligned.m8n8.x4.shared.b16 {%0,%1,%2,%3}, [%4];"
                 : "=r"(r0), "=r"(r1), "=r"(r2), "=r"(r3) : "r"(addr));
}

__device__ __forceinline__ uint32_t packbf2(float lo, float hi) {
    __nv_bfloat162 v = __floats2bfloat162_rn(lo, hi);
    return *(uint32_t*)&v;
}

// -------------------- geom stats (fused boxprep) ------------------------------
__global__ void k_geomstats(const float* __restrict__ boxes,
                            const float* __restrict__ scores,
                            const float* __restrict__ feats) {
    __shared__ float bps[G * 12];
    __shared__ float red[12 * 256];
    int i = blockIdx.x, tid = threadIdx.x;

    for (int b = tid; b < G; b += 256) {
        float x = boxes[b*4+0], y = boxes[b*4+1], w = boxes[b*4+2], h = boxes[b*4+3];
        float* bp = &bps[b * 12];
        bp[0] = x;          bp[1] = y;
        bp[2] = x + w;      bp[3] = y + h;
        bp[4] = x + 0.5f*w; bp[5] = y + 0.5f*h;
        bp[6] = w * h;
        bp[7] = logf(w);    bp[8] = logf(h);  bp[9] = logf(w * h);
        bp[10] = 1.0f / w;  bp[11] = 1.0f / h;
        if (i == 0) {
            #pragma unroll
            for (int m = 0; m < 12; m++) g_bp[b * 12 + m] = bp[m];
            g_f[b * DP1] = scores[b];
        }
    }
    if (i == 0) {
        for (int idx = tid; idx < G * 64; idx += 256) {
            int r = idx >> 6, d = idx & 63;
            g_f[r * DP1 + 1 + d] = feats[idx];
        }
    }
    __syncthreads();

    BoxI bi = loadbox_p(&bps[i * 12]);
    float ls[6] = {0,0,0,0,0,0}, lq[6] = {0,0,0,0,0,0};
    for (int j = tid; j < G; j += 256) {
        BoxI bj = loadbox_p(&bps[j * 12]);
        float g[6]; geom6(bi, bj, g);
        #pragma unroll
        for (int m = 0; m < 6; m++) { ls[m] += g[m]; lq[m] += g[m]*g[m]; }
    }
    #pragma unroll
    for (int m = 0; m < 6; m++) { red[m*256 + tid] = ls[m]; red[(6+m)*256 + tid] = lq[m]; }
    __syncthreads();
    for (int s = 128; s > 0; s >>= 1) {
        if (tid < s) {
            #pragma unroll
            for (int m = 0; m < 12; m++) red[m*256 + tid] += red[m*256 + tid + s];
        }
        __syncthreads();
    }
    if (tid == 0) {
        #pragma unroll
        for (int m = 0; m < 12; m++) g_gpart[i*12 + m] = red[m*256];
    }
}

// fused: (first: geomred) + f stats + BN0-fold into W0
__global__ void k_fstats_prepw(const float* __restrict__ W0k, const float* __restrict__ b0k,
                               const float* __restrict__ g0k, const float* __restrict__ bb0k,
                               int first) {
    __shared__ float sred[2][8][DP1 + 1];
    __shared__ float part[8][128];
    __shared__ float ws[12];
    int x = threadIdx.x, y = threadIdx.y;
    int t = y * 128 + x;

    if (first && t < 384) {
        int m = t >> 5, l = t & 31;
        float s = 0.0f;
        for (int i = l; i < G; i += 32) s += g_gpart[i * 12 + m];
        #pragma unroll
        for (int d = 16; d > 0; d >>= 1) s += __shfl_xor_sync(0xffffffffu, s, d);
        if (l == 0) ws[m] = s;
    }
    {
        int col = t & 127, chunk = t >> 7;
        if (col < DP1) {
            float s = 0.0f, q = 0.0f;
            #pragma unroll 8
            for (int r = chunk * 64; r < chunk * 64 + 64; r++) {
                float v = g_f[r * DP1 + col];
                s += v; q = fmaf(v, v, q);
            }
            sred[0][chunk][col] = s;
            sred[1][chunk][col] = q;
        }
    }
    __syncthreads();
    if (first && t < 6) {
        float mean = ws[t] * INV_N;
        float var  = fmaxf(ws[6 + t] * INV_N - mean * mean, 0.0f);
        g_geomstat[t] = mean; g_geomstat[6 + t] = var;
    }
    if (t < DP1) {
        float s = 0.0f, q = 0.0f;
        #pragma unroll
        for (int k = 0; k < 8; k++) { s += sred[0][k][t]; q += sred[1][k][t]; }
        float mean = s * INV_G;
        float var  = fmaxf(q * INV_G - mean * mean, 0.0f);
        g_fstat[t] = mean; g_fstat[DP1 + t] = var;
    }
    __syncthreads();

    int c = x, yy = y;
    float cb = 0.0f;
    int r0 = yy * 17;
    #pragma unroll
    for (int rr = 0; rr < 17; rr++) {
        int r = r0 + rr;
        float m, vv;
        if (r < 6) { m = g_geomstat[r]; vv = g_geomstat[6 + r]; }
        else       { int d = (r < 71) ? r - 6 : r - 71;
                     m = g_fstat[d];   vv = g_fstat[DP1 + d]; }
        float s0 = g0k[r] * rsqrtf(vv + EPS);
        float sh = bb0k[r] - m * s0;
        float wv = W0k[r * H + c];
        cb += sh * wv;
        if (r < 6) g_W0g[r * H + c] = s0 * wv;
    }
    part[yy][c] = cb;
    __syncthreads();
    if (yy == 0) {
        float tt = b0k[c];
        #pragma unroll
        for (int k = 0; k < 8; k++) tt += part[k][c];
        g_cb[c] = tt;
    }
}

// u'[i,c], v'[j,c] with separable geometry folded in
__global__ void k_uv(const float* __restrict__ W0k, const float* __restrict__ g0k) {
    __shared__ float fi[DP1], sA[DP1], sB[DP1];
    int i = blockIdx.x, c = threadIdx.x;
    if (c < DP1) {
        fi[c] = g_f[i * DP1 + c];
        float rs = rsqrtf(g_fstat[DP1 + c] + EPS);
        sA[c] = g0k[6 + c]  * rs;
        sB[c] = g0k[71 + c] * rs;
    }
    __syncthreads();
    float u = g_cb[c], v = 0.0f;
    for (int d = 0; d < DP1; d++) {
        float fd = fi[d];
        u = fmaf(fd * sA[d], W0k[(6  + d) * H + c], u);
        v = fmaf(fd * sB[d], W0k[(71 + d) * H + c], v);
    }
    const float* bp = &g_bp[i * 12];
    float cxr = bp[4] * bp[10], cyr = bp[5] * bp[11];
    float lw = bp[7], lh = bp[8], la = bp[9];
    float w1 = g_W0g[H + c],     w2 = g_W0g[2*H + c];
    float w3 = g_W0g[3*H + c],   w4 = g_W0g[4*H + c], w5 = g_W0g[5*H + c];
    float sep = lw * w3 + lh * w4 + la * w5;
    u += cxr * w1 + cyr * w2 - sep;
    v += sep;
    g_u[i * H + c] = u;
    g_v[i * H + c] = v;
}

// -------------------- main pair kernel (pipelined bf16 mma) ------------------
__global__ void __launch_bounds__(128, 4) k_main(const float* __restrict__ W1k,
                                                 const float* __restrict__ b1k) {
    extern __shared__ uint32_t smu[];
    uint32_t* W1p = smu;                                   // [H][SWP]
    uint32_t* h1p = smu + W1_U32;                          // [2][JT][SWP]
    float*    mask_s = (float*)(smu + W1_U32 + H1_U32);    // [2][JT]

    int i = blockIdx.x, tid = threadIdx.x;
    int lane = tid & 31, wrp = tid >> 5;
    int gid = lane >> 2, tig = lane & 3;
    int nbase = wrp * 32;
    int cpair = tid & 63;
    int half  = tid >> 6;

    {
        int c = tid;
        #pragma unroll 8
        for (int kk = 0; kk < 64; kk++)
            W1p[c * SWP + kk] = packbf2(W1k[(2 * kk) * H + c],
                                        W1k[(2 * kk + 1) * H + c]);
    }

    uint32_t h1_base = (uint32_t)__cvta_generic_to_shared(h1p);
    uint32_t w1_base = (uint32_t)__cvta_generic_to_shared(W1p);
    uint32_t aaddr[2], baddr[2];
    #pragma unroll
    for (int mi = 0; mi < 2; mi++)
        aaddr[mi] = h1_base
            + (((mi * 16 + (lane & 15)) * SWP + ((lane >> 4) << 2)) << 2);
    #pragma unroll
    for (int bi = 0; bi < 2; bi++)
        baddr[bi] = w1_base
            + (((nbase + bi * 16 + (lane & 7) + ((lane >> 4) << 3)) * SWP
                + (((lane >> 3) & 1) << 2)) << 2);

    const float* bpi = &g_bp[i * 12];
    float4 bi0 = *(const float4*)bpi;
    float ari = bpi[6], rwi = bpi[10], rhi = bpi[11];
    float ua = g_u[i * H + 2 * cpair];
    float ub = g_u[i * H + 2 * cpair + 1];
    float wioua = g_W0g[2 * cpair],           wioub = g_W0g[2 * cpair + 1];
    float wdxa = -rwi * g_W0g[H + 2*cpair],   wdxb = -rwi * g_W0g[H + 2*cpair + 1];
    float wdya = -rhi * g_W0g[2*H + 2*cpair], wdyb = -rhi * g_W0g[2*H + 2*cpair + 1];

    float bias[4][2];
    #pragma unroll
    for (int ni = 0; ni < 4; ni++)
        #pragma unroll
        for (int q = 0; q < 2; q++)
            bias[ni][q] = b1k[nbase + ni * 8 + 2 * tig + q];

    float S[4][2], Qa[4][2], Mx[4][2], Mn[4][2];
    #pragma unroll
    for (int ni = 0; ni < 4; ni++)
        #pragma unroll
        for (int q = 0; q < 2; q++) {
            S[ni][q] = 0.0f; Qa[ni][q] = 0.0f;
            Mx[ni][q] = -INFINITY; Mn[ni][q] = INFINITY;
        }

    auto produce = [&](int t, int b) {
        int j0 = t * JT;
        int jl = half * 16 + (lane & 15);
        const float* bpj = &g_bp[(j0 + jl) * 12];
        float4 j0f = *(const float4*)bpj;
        float4 j1f = *(const float4*)(bpj + 4);
        float ix1 = fmaxf(bi0.x, j0f.x), iy1 = fmaxf(bi0.y, j0f.y);
        float ix2 = fminf(bi0.z, j0f.z), iy2 = fminf(bi0.w, j0f.w);
        float inter = fmaxf(ix2 - ix1, 0.0f) * fmaxf(iy2 - iy1, 0.0f);
        float iou = inter / (ari + j1f.z - inter + 1e-6f);
        float cxj = j1f.x, cyj = j1f.y;
        if ((wrp & 1) == 0 && lane < 16)
            mask_s[b * JT + jl] = (iou > IOU_T) ? 1.0f : 0.0f;
        #pragma unroll
        for (int jj = 0; jj < 16; jj++) {
            float io = __shfl_sync(0xffffffffu, iou, jj);
            float cj = __shfl_sync(0xffffffffu, cxj, jj);
            float dj = __shfl_sync(0xffffffffu, cyj, jj);
            int j = half * 16 + jj;
            float2 vf = *(const float2*)&g_v[(j0 + j) * H + 2 * cpair];
            float a0 = ua + vf.x, a1 = ub + vf.y;
            a0 = fmaf(io, wioua, a0);  a1 = fmaf(io, wioub, a1);
            a0 = fmaf(cj, wdxa, a0);   a1 = fmaf(cj, wdxb, a1);
            a0 = fmaf(dj, wdya, a0);   a1 = fmaf(dj, wdyb, a1);
            h1p[(b * JT + j) * SWP + cpair] = packbf2(fmaxf(a0, 0.0f),
                                                      fmaxf(a1, 0.0f));
        }
    };

    produce(0, 0);

    for (int t = 0; t < 16; t++) {
        __syncthreads();
        if (t < 15) produce(t + 1, (t + 1) & 1);

        uint32_t boff = (t & 1) * H1B;

        float acc[2][4][4];
        #pragma unroll
        for (int mi = 0; mi < 2; mi++)
            #pragma unroll
            for (int ni = 0; ni < 4; ni++)
                #pragma unroll
                for (int q = 0; q < 4; q++) acc[mi][ni][q] = 0.0f;

        #pragma unroll
        for (int ki = 0; ki < 8; ki++) {
            uint32_t a[2][4], b[4][2];
            #pragma unroll
            for (int mi = 0; mi < 2; mi++)
                ldmx4(a[mi][0], a[mi][1], a[mi][2], a[mi][3],
                      aaddr[mi] + boff + ki * 32);
            #pragma unroll
            for (int bj = 0; bj < 2; bj++)
                ldmx4(b[2*bj][0], b[2*bj][1], b[2*bj+1][0], b[2*bj+1][1],
                      baddr[bj] + ki * 32);
            #pragma unroll
            for (int mi = 0; mi < 2; mi++)
                #pragma unroll
                for (int ni = 0; ni < 4; ni++)
                    mma_bf16(acc[mi][ni], a[mi], b[ni]);
        }

        #pragma unroll
        for (int mi = 0; mi < 2; mi++) {
            float m0 = mask_s[(t & 1) * JT + mi * 16 + gid];
            float m1 = mask_s[(t & 1) * JT + mi * 16 + gid + 8];
            #pragma unroll
            for (int ni = 0; ni < 4; ni++) {
                #pragma unroll
                for (int q = 0; q < 2; q++) {
                    float h0 = fmaxf(acc[mi][ni][q]     + bias[ni][q], 0.0f);
                    float h1 = fmaxf(acc[mi][ni][q + 2] + bias[ni][q], 0.0f);
                    S[ni][q] += h0 + h1;
                    Qa[ni][q] = fmaf(h0, h0, Qa[ni][q]);
                    Qa[ni][q] = fmaf(h1, h1, Qa[ni][q]);
                    if (m0 > 0.5f) { Mx[ni][q] = fmaxf(Mx[ni][q], h0); Mn[ni][q] = fminf(Mn[ni][q], h0); }
                    if (m1 > 0.5f) { Mx[ni][q] = fmaxf(Mx[ni][q], h1); Mn[ni][q] = fminf(Mn[ni][q], h1); }
                }
            }
        }
    }

    #pragma unroll
    for (int ni = 0; ni < 4; ni++)
        #pragma unroll
        for (int q = 0; q < 2; q++) {
            #pragma unroll
            for (int d = 4; d <= 16; d <<= 1) {
                S[ni][q]  += __shfl_xor_sync(0xffffffffu, S[ni][q],  d);
                Qa[ni][q] += __shfl_xor_sync(0xffffffffu, Qa[ni][q], d);
                Mx[ni][q] = fmaxf(Mx[ni][q], __shfl_xor_sync(0xffffffffu, Mx[ni][q], d));
                Mn[ni][q] = fminf(Mn[ni][q], __shfl_xor_sync(0xffffffffu, Mn[ni][q], d));
            }
        }
    if (gid == 0) {
        #pragma unroll
        for (int ni = 0; ni < 4; ni++)
            #pragma unroll
            for (int q = 0; q < 2; q++) {
                int c = nbase + ni * 8 + 2 * tig + q;
                g_sums[i * H + c]  = S[ni][q];
                g_sumsq[i * H + c] = Qa[ni][q];
                g_maxv[i * H + c]  = Mx[ni][q];
                g_minv[i * H + c]  = Mn[ni][q];
            }
    }
}

// -------------------- BN1 finalize: one block per column ---------------------
__global__ void k_bn1red(const float* __restrict__ g1k, const float* __restrict__ b1nk) {
    __shared__ float ps[256], pq[256];
    int c = blockIdx.x, t = threadIdx.x;
    float s = g_sums[t * H + c]  + g_sums[(t + 256) * H + c];
    float q = g_sumsq[t * H + c] + g_sumsq[(t + 256) * H + c];
    ps[t] = s; pq[t] = q;
    __syncthreads();
    for (int st = 128; st > 0; st >>= 1) {
        if (t < st) { ps[t] += ps[t + st]; pq[t] += pq[t + st]; }
        __syncthreads();
    }
    if (t == 0) {
        float mean = ps[0] * INV_N;
        float var  = fmaxf(pq[0] * INV_N - mean * mean, 0.0f);
        float sc = g1k[c] * rsqrtf(var + EPS);
        g_bn1[c]     = sc;
        g_bn1[H + c] = b1nk[c] - mean * sc;
    }
}

__global__ void k_fout(const float* __restrict__ Woutk, const float* __restrict__ boutk) {
    __shared__ float p[H];
    int i = blockIdx.x, t = threadIdx.x;
    float sc = g_bn1[t];
    p[t] = ((sc >= 0.0f) ? sc * g_maxv[i * H + t] : sc * g_minv[i * H + t]) + g_bn1[H + t];
    __syncthreads();
    if (t < DP1) {
        float acc = boutk[t];
        for (int c = 0; c < H; c++) acc = fmaf(p[c], Woutk[c * DP1 + t], acc);
        g_f[i * DP1 + t] = acc;
    }
}

// k=1 epilogue: pooled @ Wout then final MLP, fused
__global__ void k_fout_final(const float* __restrict__ Woutk, const float* __restrict__ boutk,
                             const float* __restrict__ Wf0, const float* __restrict__ bf0,
                             const float* __restrict__ Wf1, const float* __restrict__ bf1,
                             const float* __restrict__ Wsc, const float* __restrict__ bsc,
                             float* __restrict__ out) {
    __shared__ float p[H], fr[DP1], y1[FH], rb[FH];
    int i = blockIdx.x, t = threadIdx.x;
    float sc = g_bn1[t];
    p[t] = ((sc >= 0.0f) ? sc * g_maxv[i * H + t] : sc * g_minv[i * H + t]) + g_bn1[H + t];
    __syncthreads();
    if (t < DP1) {
        float acc = boutk[t];
        for (int c = 0; c < H; c++) acc = fmaf(p[c], Woutk[c * DP1 + t], acc);
        fr[t] = acc;
    }
    __syncthreads();
    float a = bf0[t];
    for (int d = 0; d < DP1; d++) a = fmaf(fr[d], Wf0[d * FH + t], a);
    y1[t] = fmaxf(a, 0.0f);
    __syncthreads();
    float b = bf1[t];
    for (int d = 0; d < FH; d++) b = fmaf(y1[d], Wf1[d * FH + t], b);
    float y2 = fmaxf(b, 0.0f);
    rb[t] = y2 * Wsc[t];
    __syncthreads();
    for (int s = 64; s > 0; s >>= 1) {
        if (t < s) rb[t] += rb[t + s];
        __syncthreads();
    }
    if (t == 0) out[i] = 1.0f / (1.0f + expf(-(rb[0] + bsc[0])));
}

// -------------------- launch -------------------------------------------------
extern "C" void kernel_launch(void* const* d_in, const int* in_sizes, int n_in,
                              void* d_out, int out_size) {
    const float* boxes  = (const float*)d_in[0];
    const float* scores = (const float*)d_in[1];
    const float* feats  = (const float*)d_in[2];
    const float* bn0_g  = (const float*)d_in[3];
    const float* bn0_b  = (const float*)d_in[4];
    const float* W0     = (const float*)d_in[5];
    const float* b0     = (const float*)d_in[6];
    const float* W1     = (const float*)d_in[7];
    const float* b1     = (const float*)d_in[8];
    const float* bn1_g  = (const float*)d_in[9];
    const float* bn1_b  = (const float*)d_in[10];
    const float* Wout   = (const float*)d_in[11];
    const float* bout   = (const float*)d_in[12];
    const float* Wf0    = (const float*)d_in[13];
    const float* bf0    = (const float*)d_in[14];
    const float* Wf1    = (const float*)d_in[15];
    const float* bf1    = (const float*)d_in[16];
    const float* Wsc    = (const float*)d_in[17];
    const float* bsc    = (const float*)d_in[18];
    float* out = (float*)d_out;

    cudaFuncSetAttribute(k_main, cudaFuncAttributeMaxDynamicSharedMemorySize,
                         SMEM_MAIN);

    k_geomstats<<<512, 256>>>(boxes, scores, feats);

    for (int k = 0; k < 2; k++) {
        const float* W0k   = W0 + (size_t)k * P * H;
        const float* b0k   = b0 + k * H;
        const float* g0k   = bn0_g + k * P;
        const float* bb0k  = bn0_b + k * P;
        const float* W1k   = W1 + (size_t)k * H * H;
        const float* b1k   = b1 + k * H;
        const float* g1k   = bn1_g + k * H;
        const float* b1nk  = bn1_b + k * H;
        const float* Woutk = Wout + (size_t)k * H * DP1;
        const float* boutk = bout + k * DP1;

        k_fstats_prepw<<<1, dim3(128, 8)>>>(W0k, b0k, g0k, bb0k, k == 0 ? 1 : 0);
        k_uv<<<512, 128>>>(W0k, g0k);
        k_main<<<512, 128, SMEM_MAIN>>>(W1k, b1k);
        k_bn1red<<<128, 256>>>(g1k, b1nk);
        if (k == 0)
            k_fout<<<512, 128>>>(Woutk, boutk);
        else
            k_fout_final<<<512, 128>>>(Woutk, boutk, Wf0, bf0, Wf1, bf1,
                                       Wsc, bsc, out);
    }
}